// round 15
// baseline (speedup 1.0000x reference)
#include <cuda_runtime.h>
#include <cuda_fp16.h>
#include <cstdint>

#define BSZ   2
#define QLEN  2048
#define DIM   2048
#define NH    16
#define DHD   128
#define MTOK  (BSZ * QLEN)   // 4096

// ---------------- scratch (static device memory; no allocation) -------------
__device__ __half g_xh[(size_t)MTOK * DIM];          // fp16 input
__device__ __half g_wh[4][(size_t)DIM * DIM];        // fp16 weights
__device__ __half g_qh[(size_t)MTOK * DIM];          // fp16 Q
__device__ __half g_kh[(size_t)MTOK * DIM];          // fp16 K
__device__ __half g_vh[(size_t)MTOK * DIM];          // fp16 V
__device__ __half g_ctxh[(size_t)MTOK * DIM];        // fp16 ctx

// ======================= helpers =============================================
#define CP_ASYNC16(dst, src) \
    asm volatile("cp.async.cg.shared.global [%0], [%1], 16;" :: "r"(dst), "l"(src))
#define CP_COMMIT() asm volatile("cp.async.commit_group;" ::: "memory")
#define CP_WAIT(n)  asm volatile("cp.async.wait_group %0;" :: "n"(n) : "memory")

__device__ __forceinline__ uint32_t smem_u32(const void* p) {
    uint32_t a;
    asm("{ .reg .u64 t; cvta.to.shared.u64 t, %1; cvt.u32.u64 %0, t; }"
        : "=r"(a) : "l"(p));
    return a;
}

__device__ __forceinline__ void mma_fp16(float* c, const uint32_t* a,
                                         uint32_t b0, uint32_t b1) {
    asm volatile(
        "mma.sync.aligned.m16n8k16.row.col.f32.f16.f16.f32 "
        "{%0,%1,%2,%3}, {%4,%5,%6,%7}, {%8,%9}, {%0,%1,%2,%3};"
        : "+f"(c[0]), "+f"(c[1]), "+f"(c[2]), "+f"(c[3])
        : "r"(a[0]), "r"(a[1]), "r"(a[2]), "r"(a[3]), "r"(b0), "r"(b1));
}

#define LDSM_X4(r0, r1, r2, r3, addr) \
    asm volatile("ldmatrix.sync.aligned.m8n8.x4.shared.b16 {%0,%1,%2,%3}, [%4];" \
        : "=r"(r0), "=r"(r1), "=r"(r2), "=r"(r3) : "r"(addr))
#define LDSM_X4T(r0, r1, r2, r3, addr) \
    asm volatile("ldmatrix.sync.aligned.m8n8.x4.trans.shared.b16 {%0,%1,%2,%3}, [%4];" \
        : "=r"(r0), "=r"(r1), "=r"(r2), "=r"(r3) : "r"(addr))

// ------------- fused fp32 -> fp16 conversion (all 5 tensors) ----------------
__global__ __launch_bounds__(256) void cvt_all(
    const float4* __restrict__ x,  const float4* __restrict__ w0,
    const float4* __restrict__ w1, const float4* __restrict__ w2,
    const float4* __restrict__ w3,
    uint2* __restrict__ ox,  uint2* __restrict__ o0, uint2* __restrict__ o1,
    uint2* __restrict__ o2,  uint2* __restrict__ o3,
    int nx4, int nw4)
{
    const int seg = blockIdx.y;
    const float4* in  = (seg == 0) ? x  : (seg == 1) ? w0 : (seg == 2) ? w1
                        : (seg == 3) ? w2 : w3;
    uint2* out        = (seg == 0) ? ox : (seg == 1) ? o0 : (seg == 2) ? o1
                        : (seg == 3) ? o2 : o3;
    const int n4      = (seg == 0) ? nx4 : nw4;
    int i = blockIdx.x * 256 + threadIdx.x;
    if (i < n4) {
        float4 v = in[i];
        __half2 h0 = __floats2half2_rn(v.x, v.y);
        __half2 h1 = __floats2half2_rn(v.z, v.w);
        out[i] = make_uint2(*(uint32_t*)&h0, *(uint32_t*)&h1);
    }
}

// ======================= shared GEMM constants ==============================
#define HPITCH   72                          // halves/row (144B = 36w ==4 mod 32)
#define A_HALVES (128 * HPITCH)              // 9216
#define TILE_BYTES (A_HALVES * 2)            // 18432 per 128-row tile

// ================ fused QKV GEMM: {Q,K,V} = x @ W{q,k,v}^T + b ==============
// CTA 128(m) x 128(n) x 3 outputs. A tile loaded ONCE, reused for all three.
// Stage = A + W0 + W1 + W2 = 73.7KB; 3 stages = 221KB smem, occ 1 (regs ~240).
#define QSTAGE_BYTES (4 * TILE_BYTES)        // 73728
#define QNSTAGE  3
#define QSMEM_BYTES (QNSTAGE * QSTAGE_BYTES) // 221184

__global__ __launch_bounds__(256, 1) void gemm_qkv_fused(
    const __half* __restrict__ A,
    const __half* __restrict__ W0, const __half* __restrict__ W1, const __half* __restrict__ W2,
    const float* __restrict__ b0, const float* __restrict__ b1, const float* __restrict__ b2,
    __half* __restrict__ C0, __half* __restrict__ C1, __half* __restrict__ C2)
{
    extern __shared__ char smc[];
    const uint32_t sb = smem_u32(smc);
    const int tid  = threadIdx.x;
    const int wid  = tid >> 5, lane = tid & 31;
    const int g    = lane >> 2, t = lane & 3;
    const int wm   = wid >> 2;          // 0..1
    const int wn   = wid & 3;           // 0..3
    const int m0   = blockIdx.y * 128;
    const int n0   = blockIdx.x * 128;
    const int NT   = DIM >> 6;          // 32

    const uint32_t aoff  = ((wm * 64 + (lane & 15)) * HPITCH + 8 * (lane >> 4)) * 2;
    const uint32_t boffr = ((wn * 32 + (lane & 7) + 8 * (lane >> 4)) * HPITCH
                            + 8 * ((lane >> 3) & 1)) * 2;

    const __half* base0 = A  + (size_t)m0 * DIM;
    const __half* base1 = W0 + (size_t)n0 * DIM;
    const __half* base2 = W1 + (size_t)n0 * DIM;
    const __half* base3 = W2 + (size_t)n0 * DIM;

    auto load_stage = [&](int s) {
        uint32_t soff = sb + (s % QNSTAGE) * QSTAGE_BYTES;
        const __half* Ag = base0 + s * 64;
        const __half* G1 = base1 + s * 64;
        const __half* G2 = base2 + s * 64;
        const __half* G3 = base3 + s * 64;
#pragma unroll
        for (int i = 0; i < 16; ++i) {
            int c  = tid + i * 256;            // 0..4095
            int tl = c >> 10;                  // 0..3
            int c2 = c & 1023;
            int row = c2 >> 3, kc = c2 & 7;
            const __half* src = (tl == 0) ? Ag : (tl == 1) ? G1 : (tl == 2) ? G2 : G3;
            CP_ASYNC16(soff + tl * TILE_BYTES + (row * HPITCH + kc * 8) * 2,
                       src + (size_t)row * DIM + kc * 8);
        }
        CP_COMMIT();
    };

    float acc[3][4][4][4];
#pragma unroll
    for (int w = 0; w < 3; ++w)
#pragma unroll
        for (int mt = 0; mt < 4; ++mt)
#pragma unroll
            for (int nf = 0; nf < 4; ++nf)
#pragma unroll
                for (int q = 0; q < 4; ++q) acc[w][mt][nf][q] = 0.f;

    load_stage(0); load_stage(1);

    for (int tt = 0; tt < NT; ++tt) {
        CP_WAIT(1);
        __syncthreads();
        if (tt + 2 < NT) load_stage(tt + 2);
        else CP_COMMIT();

        const uint32_t stg = sb + (tt % QNSTAGE) * QSTAGE_BYTES;

#pragma unroll
        for (int k16 = 0; k16 < 4; ++k16) {
            const uint32_t kb = k16 * 32;      // 16 halves
            uint32_t a[4][4];
#pragma unroll
            for (int mt = 0; mt < 4; ++mt)
                LDSM_X4(a[mt][0], a[mt][1], a[mt][2], a[mt][3],
                        stg + aoff + mt * (16 * HPITCH * 2) + kb);
#pragma unroll
            for (int w = 0; w < 3; ++w) {
                uint32_t bb[2][4];
#pragma unroll
                for (int p = 0; p < 2; ++p)
                    LDSM_X4(bb[p][0], bb[p][1], bb[p][2], bb[p][3],
                            stg + (1 + w) * TILE_BYTES + boffr
                                + p * (16 * HPITCH * 2) + kb);
#pragma unroll
                for (int nf = 0; nf < 4; ++nf) {
                    uint32_t bv0 = bb[nf >> 1][(nf & 1) * 2];
                    uint32_t bv1 = bb[nf >> 1][(nf & 1) * 2 + 1];
                    mma_fp16(acc[w][0][nf], a[0], bv0, bv1);
                    mma_fp16(acc[w][1][nf], a[1], bv0, bv1);
                    mma_fp16(acc[w][2][nf], a[2], bv0, bv1);
                    mma_fp16(acc[w][3][nf], a[3], bv0, bv1);
                }
            }
        }
    }

#pragma unroll
    for (int w = 0; w < 3; ++w) {
        const float* bias = (w == 0) ? b0 : (w == 1) ? b1 : b2;
        __half* Ch        = (w == 0) ? C0 : (w == 1) ? C1 : C2;
#pragma unroll
        for (int nf = 0; nf < 4; ++nf) {
            int col = n0 + wn * 32 + nf * 8 + t * 2;
            float2 bj = *(const float2*)&bias[col];
#pragma unroll
            for (int mt = 0; mt < 4; ++mt) {
                int r0 = m0 + wm * 64 + mt * 16 + g;
                __half2 h0 = __floats2half2_rn(acc[w][mt][nf][0] + bj.x,
                                               acc[w][mt][nf][1] + bj.y);
                __half2 h1 = __floats2half2_rn(acc[w][mt][nf][2] + bj.x,
                                               acc[w][mt][nf][3] + bj.y);
                *(uint32_t*)&Ch[(size_t)r0 * DIM + col]       = *(uint32_t*)&h0;
                *(uint32_t*)&Ch[(size_t)(r0 + 8) * DIM + col] = *(uint32_t*)&h1;
            }
        }
    }
}

// ================ output GEMM (single, proven R12 config) ===================
#define STAGE_BYTES (2 * TILE_BYTES)         // 36864 (A then W)
#define NSTAGE   3
#define GSMEM_BYTES (NSTAGE * STAGE_BYTES)   // 110592

__global__ __launch_bounds__(256, 2) void gemm_out(
    const __half* __restrict__ A, const __half* __restrict__ W,
    const float* __restrict__ bias, float* __restrict__ C)
{
    extern __shared__ char smc[];
    const uint32_t sb = smem_u32(smc);
    const int tid  = threadIdx.x;
    const int wid  = tid >> 5, lane = tid & 31;
    const int g    = lane >> 2, t = lane & 3;
    const int wm   = wid >> 2;
    const int wn   = wid & 3;
    const int m0   = blockIdx.y * 128;
    const int n0   = blockIdx.x * 128;
    const int NT   = DIM >> 6;

    const uint32_t aoff = ((wm * 64 + (lane & 15)) * HPITCH + 8 * (lane >> 4)) * 2;
    const uint32_t boff = TILE_BYTES +
        ((wn * 32 + (lane & 7) + 8 * (lane >> 4)) * HPITCH + 8 * ((lane >> 3) & 1)) * 2;

    const __half* Abase = A + (size_t)m0 * DIM;
    const __half* Wbase = W + (size_t)n0 * DIM;

    auto load_stage = [&](int s) {
        uint32_t soff = sb + (s % NSTAGE) * STAGE_BYTES;
        const __half* Ag = Abase + s * 64;
        const __half* Wg = Wbase + s * 64;
#pragma unroll
        for (int i = 0; i < 8; ++i) {
            int c = tid + i * 256;
            if (i < 4) {
                int row = c >> 3, kc = c & 7;
                CP_ASYNC16(soff + (row * HPITCH + kc * 8) * 2,
                           Ag + (size_t)row * DIM + kc * 8);
            } else {
                int c2 = c - 1024;
                int row = c2 >> 3, kc = c2 & 7;
                CP_ASYNC16(soff + TILE_BYTES + (row * HPITCH + kc * 8) * 2,
                           Wg + (size_t)row * DIM + kc * 8);
            }
        }
        CP_COMMIT();
    };

    float acc[4][4][4];
#pragma unroll
    for (int mt = 0; mt < 4; ++mt)
#pragma unroll
        for (int nf = 0; nf < 4; ++nf)
#pragma unroll
            for (int q = 0; q < 4; ++q) acc[mt][nf][q] = 0.f;

    load_stage(0); load_stage(1);

    for (int tt = 0; tt < NT; ++tt) {
        CP_WAIT(1);
        __syncthreads();
        if (tt + 2 < NT) load_stage(tt + 2);
        else CP_COMMIT();

        const uint32_t stg = sb + (tt % NSTAGE) * STAGE_BYTES;

#pragma unroll
        for (int k16 = 0; k16 < 4; ++k16) {
            const uint32_t kb = k16 * 32;
            uint32_t a[4][4];
#pragma unroll
            for (int mt = 0; mt < 4; ++mt)
                LDSM_X4(a[mt][0], a[mt][1], a[mt][2], a[mt][3],
                        stg + aoff + mt * (16 * HPITCH * 2) + kb);
            uint32_t bb[2][4];
#pragma unroll
            for (int p = 0; p < 2; ++p)
                LDSM_X4(bb[p][0], bb[p][1], bb[p][2], bb[p][3],
                        stg + boff + p * (16 * HPITCH * 2) + kb);
#pragma unroll
            for (int nf = 0; nf < 4; ++nf) {
                uint32_t b0 = bb[nf >> 1][(nf & 1) * 2];
                uint32_t b1 = bb[nf >> 1][(nf & 1) * 2 + 1];
                mma_fp16(acc[0][nf], a[0], b0, b1);
                mma_fp16(acc[1][nf], a[1], b0, b1);
                mma_fp16(acc[2][nf], a[2], b0, b1);
                mma_fp16(acc[3][nf], a[3], b0, b1);
            }
        }
    }

#pragma unroll
    for (int nf = 0; nf < 4; ++nf) {
        int col = n0 + wn * 32 + nf * 8 + t * 2;
        float2 bj = *(const float2*)&bias[col];
#pragma unroll
        for (int mt = 0; mt < 4; ++mt) {
            int r0 = m0 + wm * 64 + mt * 16 + g;
            *(float2*)&C[(size_t)r0 * DIM + col] =
                make_float2(acc[mt][nf][0] + bj.x, acc[mt][nf][1] + bj.y);
            *(float2*)&C[(size_t)(r0 + 8) * DIM + col] =
                make_float2(acc[mt][nf][2] + bj.x, acc[mt][nf][3] + bj.y);
        }
    }
}

// ================ all-fp16 flash attention (R14 config) =====================
#define ABQ 64
#define ABK 64
#define KPH 136
#define VPH 136

#define SMB_K0 0
#define SMB_K1 (SMB_K0 + ABK * KPH * 2)      // 17408
#define SMB_V0 (SMB_K1 + ABK * KPH * 2)      // 34816
#define SMB_V1 (SMB_V0 + ABK * VPH * 2)      // 52224
#define SMB_MK (SMB_V1 + ABK * VPH * 2)      // 69632
#define ATT_BYTES (SMB_MK + 512)             // 70144

__global__ __launch_bounds__(128, 3) void attn_mma(
    const __half* __restrict__ Qm, const __half* __restrict__ Km,
    const __half* __restrict__ Vm, const int* __restrict__ mask,
    __half* __restrict__ ctx)
{
    extern __shared__ char smc[];
    const uint32_t sb = smem_u32(smc);
    const int tid = threadIdx.x, wid = tid >> 5, lane = tid & 31;
    const int g = lane >> 2, t = lane & 3;
    const int b = blockIdx.z, h = blockIdx.y, q0 = blockIdx.x * ABQ;
    const int wrow = wid * 16;
    const float scale = 0.08838834764831845f;
    const int NBLK = QLEN / ABK;                // 32

    const uint32_t koff =
        (((lane & 7) + 8 * (lane >> 4)) * KPH + 8 * ((lane >> 3) & 1)) * 2;
    const uint32_t voff =
        (((lane & 7) + 8 * ((lane >> 3) & 1)) * VPH + 8 * (lane >> 4)) * 2;

    auto load_kv = [&](int blk) {
        int bi = blk & 1;
        const __half* Kg = Km + ((size_t)(b * QLEN) + blk * ABK) * DIM + h * DHD;
        const __half* Vg = Vm + ((size_t)(b * QLEN) + blk * ABK) * DIM + h * DHD;
        uint32_t kbase = sb + (bi ? SMB_K1 : SMB_K0);
        uint32_t vbase = sb + (bi ? SMB_V1 : SMB_V0);
#pragma unroll
        for (int i = 0; i < 8; ++i) {
            int c = tid + i * 128;
            int r = c >> 4, c8 = c & 15;
            CP_ASYNC16(kbase + (r * KPH + c8 * 8) * 2, Kg + (size_t)r * DIM + c8 * 8);
        }
#pragma unroll
        for (int i = 0; i < 8; ++i) {
            int c = tid + i * 128;
            int r = c >> 4, c8 = c & 15;
            CP_ASYNC16(vbase + (r * VPH + c8 * 8) * 2, Vg + (size_t)r * DIM + c8 * 8);
        }
        if (tid < 16)
            CP_ASYNC16(sb + SMB_MK + bi * 256 + tid * 16,
                       mask + b * QLEN + blk * ABK + tid * 4);
        CP_COMMIT();
    };

    uint32_t qa[8][4];
    {
        const __half* Qg = Qm + ((size_t)(b * QLEN) + q0 + wrow) * DIM + h * DHD;
#pragma unroll
        for (int kk = 0; kk < 8; ++kk) {
            int ko = kk * 16;
            qa[kk][0] = *(const uint32_t*)&Qg[(size_t)g * DIM + ko + 2 * t];
            qa[kk][1] = *(const uint32_t*)&Qg[(size_t)(g + 8) * DIM + ko + 2 * t];
            qa[kk][2] = *(const uint32_t*)&Qg[(size_t)g * DIM + ko + 8 + 2 * t];
            qa[kk][3] = *(const uint32_t*)&Qg[(size_t)(g + 8) * DIM + ko + 8 + 2 * t];
        }
    }

    float oacc[16][4];
#pragma unroll
    for (int nf = 0; nf < 16; ++nf)
#pragma unroll
        for (int q = 0; q < 4; ++q) oacc[nf][q] = 0.f;
    float mrow0 = -1e30f, mrow1 = -1e30f, lrow0 = 0.f, lrow1 = 0.f;

    load_kv(0); load_kv(1);

    for (int blk = 0; blk < NBLK; ++blk) {
        CP_WAIT(1);
        __syncthreads();
        const int bi = blk & 1;
        const uint32_t kbase = sb + (bi ? SMB_K1 : SMB_K0);
        const uint32_t vbase = sb + (bi ? SMB_V1 : SMB_V0);
        const int* mk = (const int*)(smc + SMB_MK + bi * 256);

        float sacc[8][4];
#pragma unroll
        for (int nf = 0; nf < 8; ++nf)
#pragma unroll
            for (int q = 0; q < 4; ++q) sacc[nf][q] = 0.f;

#pragma unroll
        for (int kk = 0; kk < 8; ++kk) {
            uint32_t bb[4][4];
#pragma unroll
            for (int p = 0; p < 4; ++p)
                LDSM_X4(bb[p][0], bb[p][1], bb[p][2], bb[p][3],
                        kbase + koff + p * (16 * KPH * 2) + kk * 32);
#pragma unroll
            for (int nf = 0; nf < 8; ++nf)
                mma_fp16(sacc[nf], qa[kk],
                         bb[nf >> 1][(nf & 1) * 2], bb[nf >> 1][(nf & 1) * 2 + 1]);
        }

        float pm0 = -1e30f, pm1 = -1e30f;
#pragma unroll
        for (int nf = 0; nf < 8; ++nf) {
            int j0 = nf * 8 + 2 * t, j1 = j0 + 1;
            bool a0 = mk[j0] != 0, a1 = mk[j1] != 0;
            sacc[nf][0] = a0 ? sacc[nf][0] * scale : -1e30f;
            sacc[nf][1] = a1 ? sacc[nf][1] * scale : -1e30f;
            sacc[nf][2] = a0 ? sacc[nf][2] * scale : -1e30f;
            sacc[nf][3] = a1 ? sacc[nf][3] * scale : -1e30f;
            pm0 = fmaxf(pm0, fmaxf(sacc[nf][0], sacc[nf][1]));
            pm1 = fmaxf(pm1, fmaxf(sacc[nf][2], sacc[nf][3]));
        }
        pm0 = fmaxf(pm0, __shfl_xor_sync(0xFFFFFFFFu, pm0, 1));
        pm0 = fmaxf(pm0, __shfl_xor_sync(0xFFFFFFFFu, pm0, 2));
        pm1 = fmaxf(pm1, __shfl_xor_sync(0xFFFFFFFFu, pm1, 1));
        pm1 = fmaxf(pm1, __shfl_xor_sync(0xFFFFFFFFu, pm1, 2));

        float mnew0 = fmaxf(mrow0, pm0), mnew1 = fmaxf(mrow1, pm1);
        float corr0 = __expf(mrow0 - mnew0), corr1 = __expf(mrow1 - mnew1);
#pragma unroll
        for (int nf = 0; nf < 16; ++nf) {
            oacc[nf][0] *= corr0; oacc[nf][1] *= corr0;
            oacc[nf][2] *= corr1; oacc[nf][3] *= corr1;
        }

        float ps0 = 0.f, ps1 = 0.f;
#pragma unroll
        for (int nf = 0; nf < 8; ++nf) {
            sacc[nf][0] = __expf(sacc[nf][0] - mnew0);
            sacc[nf][1] = __expf(sacc[nf][1] - mnew0);
            sacc[nf][2] = __expf(sacc[nf][2] - mnew1);
            sacc[nf][3] = __expf(sacc[nf][3] - mnew1);
            ps0 += sacc[nf][0] + sacc[nf][1];
            ps1 += sacc[nf][2] + sacc[nf][3];
        }
        ps0 += __shfl_xor_sync(0xFFFFFFFFu, ps0, 1);
        ps0 += __shfl_xor_sync(0xFFFFFFFFu, ps0, 2);
        ps1 += __shfl_xor_sync(0xFFFFFFFFu, ps1, 1);
        ps1 += __shfl_xor_sync(0xFFFFFFFFu, ps1, 2);
        lrow0 = lrow0 * corr0 + ps0;
        lrow1 = lrow1 * corr1 + ps1;
        mrow0 = mnew0; mrow1 = mnew1;

#pragma unroll
        for (int kk2 = 0; kk2 < 4; ++kk2) {
            uint32_t pa[4];
            __half2 hp;
            hp = __floats2half2_rn(sacc[2 * kk2][0],     sacc[2 * kk2][1]);     pa[0] = *(uint32_t*)&hp;
            hp = __floats2half2_rn(sacc[2 * kk2][2],     sacc[2 * kk2][3]);     pa[1] = *(uint32_t*)&hp;
            hp = __floats2half2_rn(sacc[2 * kk2 + 1][0], sacc[2 * kk2 + 1][1]); pa[2] = *(uint32_t*)&hp;
            hp = __floats2half2_rn(sacc[2 * kk2 + 1][2], sacc[2 * kk2 + 1][3]); pa[3] = *(uint32_t*)&hp;
#pragma unroll
            for (int p = 0; p < 8; ++p) {
                uint32_t v0, v1, v2, v3;
                LDSM_X4T(v0, v1, v2, v3,
                         vbase + voff + p * 32 + kk2 * (16 * VPH * 2));
                mma_fp16(oacc[2 * p],     pa, v0, v1);
                mma_fp16(oacc[2 * p + 1], pa, v2, v3);
            }
        }
        __syncthreads();
        if (blk + 2 < NBLK) load_kv(blk + 2);
        else CP_COMMIT();
    }

    float inv0 = 1.f / lrow0, inv1 = 1.f / lrow1;
    __half* Ob = ctx + ((size_t)(b * QLEN) + q0 + wrow) * DIM + h * DHD;
#pragma unroll
    for (int nf = 0; nf < 16; ++nf) {
        int col = nf * 8 + 2 * t;
        __half2 h0 = __floats2half2_rn(oacc[nf][0] * inv0, oacc[nf][1] * inv0);
        __half2 h1 = __floats2half2_rn(oacc[nf][2] * inv1, oacc[nf][3] * inv1);
        *(uint32_t*)&Ob[(size_t)g * DIM + col]       = *(uint32_t*)&h0;
        *(uint32_t*)&Ob[(size_t)(g + 8) * DIM + col] = *(uint32_t*)&h1;
    }
}

// ---------------- launch -----------------------------------------------------
extern "C" void kernel_launch(void* const* d_in, const int* in_sizes, int n_in,
                              void* d_out, int out_size)
{
    const float* x    = (const float*)d_in[0];
    const int*   mask = (const int*)d_in[1];
    const float* wq   = (const float*)d_in[2];
    const float* bq   = (const float*)d_in[3];
    const float* wk   = (const float*)d_in[4];
    const float* bk   = (const float*)d_in[5];
    const float* wv   = (const float*)d_in[6];
    const float* bv   = (const float*)d_in[7];
    const float* wo   = (const float*)d_in[8];
    const float* bo   = (const float*)d_in[9];
    float* out = (float*)d_out;

    __half *gxh, *gwh, *gqh, *gkh, *gvh, *gctxh;
    cudaGetSymbolAddress((void**)&gxh,   g_xh);
    cudaGetSymbolAddress((void**)&gwh,   g_wh);
    cudaGetSymbolAddress((void**)&gqh,   g_qh);
    cudaGetSymbolAddress((void**)&gkh,   g_kh);
    cudaGetSymbolAddress((void**)&gvh,   g_vh);
    cudaGetSymbolAddress((void**)&gctxh, g_ctxh);
    __half* gwq = gwh;
    __half* gwk = gwh + (size_t)DIM * DIM;
    __half* gwv = gwh + 2 * (size_t)DIM * DIM;
    __half* gwo = gwh + 3 * (size_t)DIM * DIM;

    const int nx4 = MTOK * DIM / 4;
    const int nw4 = DIM * DIM / 4;
    dim3 cvt_grid((nx4 + 255) / 256, 5);
    cvt_all<<<cvt_grid, 256>>>((const float4*)x, (const float4*)wq,
                               (const float4*)wk, (const float4*)wv,
                               (const float4*)wo,
                               (uint2*)gxh, (uint2*)gwq, (uint2*)gwk,
                               (uint2*)gwv, (uint2*)gwo, nx4, nw4);

    cudaFuncSetAttribute(gemm_qkv_fused, cudaFuncAttributeMaxDynamicSharedMemorySize, QSMEM_BYTES);
    cudaFuncSetAttribute(gemm_out, cudaFuncAttributeMaxDynamicSharedMemorySize, GSMEM_BYTES);
    cudaFuncSetAttribute(attn_mma, cudaFuncAttributeMaxDynamicSharedMemorySize, ATT_BYTES);

    dim3 qkv_grid(DIM / 128, MTOK / 128);      // (16, 32) = 512 CTAs
    gemm_qkv_fused<<<qkv_grid, 256, QSMEM_BYTES>>>(gxh, gwq, gwk, gwv,
                                                   bq, bk, bv, gqh, gkh, gvh);

    attn_mma<<<dim3(QLEN / ABQ, NH, BSZ), 128, ATT_BYTES>>>(gqh, gkh, gvh, mask, gctxh);

    dim3 gemm_grid(DIM / 128, MTOK / 128);     // (16, 32) = 512 CTAs
    gemm_out<<<gemm_grid, 256, GSMEM_BYTES>>>(gctxh, gwo, bo, out);
}

// round 16
// speedup vs baseline: 1.0620x; 1.0620x over previous
#include <cuda_runtime.h>
#include <cuda_fp16.h>
#include <cstdint>

#define BSZ   2
#define QLEN  2048
#define DIM   2048
#define NH    16
#define DHD   128
#define MTOK  (BSZ * QLEN)   // 4096

// ---------------- scratch (static device memory; no allocation) -------------
__device__ __half g_xh[(size_t)MTOK * DIM];          // fp16 input
__device__ __half g_wh[4][(size_t)DIM * DIM];        // fp16 weights
__device__ __half g_qh[(size_t)MTOK * DIM];          // fp16 Q
__device__ __half g_kh[(size_t)MTOK * DIM];          // fp16 K
__device__ __half g_vh[(size_t)MTOK * DIM];          // fp16 V
__device__ __half g_ctxh[(size_t)MTOK * DIM];        // fp16 ctx

// ======================= helpers =============================================
#define CP_ASYNC16(dst, src) \
    asm volatile("cp.async.cg.shared.global [%0], [%1], 16;" :: "r"(dst), "l"(src))
#define CP_COMMIT() asm volatile("cp.async.commit_group;" ::: "memory")
#define CP_WAIT(n)  asm volatile("cp.async.wait_group %0;" :: "n"(n) : "memory")

__device__ __forceinline__ uint32_t smem_u32(const void* p) {
    uint32_t a;
    asm("{ .reg .u64 t; cvta.to.shared.u64 t, %1; cvt.u32.u64 %0, t; }"
        : "=r"(a) : "l"(p));
    return a;
}

__device__ __forceinline__ void mma_fp16(float* c, const uint32_t* a,
                                         uint32_t b0, uint32_t b1) {
    asm volatile(
        "mma.sync.aligned.m16n8k16.row.col.f32.f16.f16.f32 "
        "{%0,%1,%2,%3}, {%4,%5,%6,%7}, {%8,%9}, {%0,%1,%2,%3};"
        : "+f"(c[0]), "+f"(c[1]), "+f"(c[2]), "+f"(c[3])
        : "r"(a[0]), "r"(a[1]), "r"(a[2]), "r"(a[3]), "r"(b0), "r"(b1));
}

#define LDSM_X4(r0, r1, r2, r3, addr) \
    asm volatile("ldmatrix.sync.aligned.m8n8.x4.shared.b16 {%0,%1,%2,%3}, [%4];" \
        : "=r"(r0), "=r"(r1), "=r"(r2), "=r"(r3) : "r"(addr))
#define LDSM_X4T(r0, r1, r2, r3, addr) \
    asm volatile("ldmatrix.sync.aligned.m8n8.x4.trans.shared.b16 {%0,%1,%2,%3}, [%4];" \
        : "=r"(r0), "=r"(r1), "=r"(r2), "=r"(r3) : "r"(addr))

// ------------- flat fused fp32 -> fp16 conversion (all 5 tensors) -----------
#define NX4 (MTOK * DIM / 4)    // 2,097,152
#define NW4 (DIM * DIM / 4)     // 1,048,576
#define NTOT4 (NX4 + 4 * NW4)   // 6,291,456

__global__ __launch_bounds__(256) void cvt_flat(
    const float4* __restrict__ x,  const float4* __restrict__ w0,
    const float4* __restrict__ w1, const float4* __restrict__ w2,
    const float4* __restrict__ w3,
    uint2* __restrict__ ox,  uint2* __restrict__ o0, uint2* __restrict__ o1,
    uint2* __restrict__ o2,  uint2* __restrict__ o3)
{
    int i = blockIdx.x * 256 + threadIdx.x;
    if (i >= NTOT4) return;
    const float4* in;
    uint2* out;
    int off;
    if (i < NX4) { in = x; out = ox; off = i; }
    else {
        int j = i - NX4;
        int seg = j / NW4;                 // compile-time divisor
        off = j - seg * NW4;
        in  = (seg == 0) ? w0 : (seg == 1) ? w1 : (seg == 2) ? w2 : w3;
        out = (seg == 0) ? o0 : (seg == 1) ? o1 : (seg == 2) ? o2 : o3;
    }
    float4 v = in[off];
    __half2 h0 = __floats2half2_rn(v.x, v.y);
    __half2 h1 = __floats2half2_rn(v.z, v.w);
    out[off] = make_uint2(*(uint32_t*)&h0, *(uint32_t*)&h1);
}

// ================ fp16 mma GEMM: C = A @ W^T + bias =========================
// CTA 128(m) x 128(n), BK=64 halves. 8 warps (2m x 4n), warp tile 64x32.
// ldmatrix.x4 fragment loads. 3-stage cp.async ring, 110.6KB smem -> 2 CTA/SM.
#define HPITCH   72                          // halves/row (144B = 36w ==4 mod 32)
#define A_HALVES (128 * HPITCH)              // 9216
#define STAGE_BYTES (2 * A_HALVES * 2)       // 36864 (A then W)
#define NSTAGE   3
#define GSMEM_BYTES (NSTAGE * STAGE_BYTES)   // 110592

// MODE: 0 = float out, 1 = half out
template <int MODE>
__device__ __forceinline__ void gemm_body(
    const __half* __restrict__ A, const __half* __restrict__ W,
    const float* __restrict__ bias, void* __restrict__ Cv,
    int M, int N, int K)
{
    extern __shared__ char smc[];
    const uint32_t sb = smem_u32(smc);
    const int tid  = threadIdx.x;
    const int wid  = tid >> 5, lane = tid & 31;
    const int g    = lane >> 2, t = lane & 3;
    const int wm   = wid >> 2;          // 0..1
    const int wn   = wid & 3;           // 0..3
    const int m0   = blockIdx.y * 128;
    const int n0   = blockIdx.x * 128;
    const int NT   = K >> 6;            // 32

    const uint32_t aoff = ((wm * 64 + (lane & 15)) * HPITCH + 8 * (lane >> 4)) * 2;
    const uint32_t boff = A_HALVES * 2 +
        ((wn * 32 + (lane & 7) + 8 * (lane >> 4)) * HPITCH + 8 * ((lane >> 3) & 1)) * 2;

    const __half* Abase = A + (size_t)m0 * K;
    const __half* Wbase = W + (size_t)n0 * K;

    auto load_stage = [&](int s) {
        uint32_t soff = sb + (s % NSTAGE) * STAGE_BYTES;
        const __half* Ag = Abase + s * 64;
        const __half* Wg = Wbase + s * 64;
#pragma unroll
        for (int i = 0; i < 8; ++i) {
            int c = tid + i * 256;             // 0..2047
            if (i < 4) {                        // A: 1024 chunks (128 rows x 8)
                int row = c >> 3, kc = c & 7;
                CP_ASYNC16(soff + (row * HPITCH + kc * 8) * 2,
                           Ag + (size_t)row * K + kc * 8);
            } else {                            // W: 1024 chunks
                int c2 = c - 1024;
                int row = c2 >> 3, kc = c2 & 7;
                CP_ASYNC16(soff + A_HALVES * 2 + (row * HPITCH + kc * 8) * 2,
                           Wg + (size_t)row * K + kc * 8);
            }
        }
        CP_COMMIT();
    };

    float acc[4][4][4];
#pragma unroll
    for (int mt = 0; mt < 4; ++mt)
#pragma unroll
        for (int nf = 0; nf < 4; ++nf)
#pragma unroll
            for (int q = 0; q < 4; ++q) acc[mt][nf][q] = 0.f;

    load_stage(0); load_stage(1);

    for (int tt = 0; tt < NT; ++tt) {
        CP_WAIT(1);
        __syncthreads();
        if (tt + 2 < NT) load_stage(tt + 2);
        else CP_COMMIT();

        const uint32_t stg = sb + (tt % NSTAGE) * STAGE_BYTES;

#pragma unroll
        for (int k16 = 0; k16 < 4; ++k16) {
            const uint32_t kb = k16 * 32;      // 16 halves
            uint32_t a[4][4];
#pragma unroll
            for (int mt = 0; mt < 4; ++mt)
                LDSM_X4(a[mt][0], a[mt][1], a[mt][2], a[mt][3],
                        stg + aoff + mt * (16 * HPITCH * 2) + kb);
            uint32_t bb[2][4];
#pragma unroll
            for (int p = 0; p < 2; ++p)
                LDSM_X4(bb[p][0], bb[p][1], bb[p][2], bb[p][3],
                        stg + boff + p * (16 * HPITCH * 2) + kb);
#pragma unroll
            for (int nf = 0; nf < 4; ++nf) {
                uint32_t b0 = bb[nf >> 1][(nf & 1) * 2];
                uint32_t b1 = bb[nf >> 1][(nf & 1) * 2 + 1];
                mma_fp16(acc[0][nf], a[0], b0, b1);
                mma_fp16(acc[1][nf], a[1], b0, b1);
                mma_fp16(acc[2][nf], a[2], b0, b1);
                mma_fp16(acc[3][nf], a[3], b0, b1);
            }
        }
    }

#pragma unroll
    for (int nf = 0; nf < 4; ++nf) {
        int col = n0 + wn * 32 + nf * 8 + t * 2;
        float2 bj = *(const float2*)&bias[col];
#pragma unroll
        for (int mt = 0; mt < 4; ++mt) {
            int r0 = m0 + wm * 64 + mt * 16 + g;
            float o0 = acc[mt][nf][0] + bj.x, o1 = acc[mt][nf][1] + bj.y;
            float o2 = acc[mt][nf][2] + bj.x, o3 = acc[mt][nf][3] + bj.y;
            if (MODE == 1) {
                __half* Ch = (__half*)Cv;
                __half2 h0 = __floats2half2_rn(o0, o1);
                __half2 h1 = __floats2half2_rn(o2, o3);
                *(uint32_t*)&Ch[(size_t)r0 * N + col]       = *(uint32_t*)&h0;
                *(uint32_t*)&Ch[(size_t)(r0 + 8) * N + col] = *(uint32_t*)&h1;
            } else {
                float* Cf = (float*)Cv;
                *(float2*)&Cf[(size_t)r0 * N + col]       = make_float2(o0, o1);
                *(float2*)&Cf[(size_t)(r0 + 8) * N + col] = make_float2(o2, o3);
            }
        }
    }
}

__global__ __launch_bounds__(256, 2) void gemm_qkv(
    const __half* __restrict__ A,
    const __half* __restrict__ W0, const __half* __restrict__ W1, const __half* __restrict__ W2,
    const float* __restrict__ b0, const float* __restrict__ b1, const float* __restrict__ b2,
    __half* __restrict__ C0, __half* __restrict__ C1, __half* __restrict__ C2)
{
    const int z = blockIdx.z;
    const __half* W = (z == 0) ? W0 : (z == 1) ? W1 : W2;
    const float*  B = (z == 0) ? b0 : (z == 1) ? b1 : b2;
    __half*       C = (z == 0) ? C0 : (z == 1) ? C1 : C2;
    gemm_body<1>(A, W, B, C, MTOK, DIM, DIM);
}

__global__ __launch_bounds__(256, 2) void gemm_out(
    const __half* __restrict__ A, const __half* __restrict__ W,
    const float* __restrict__ bias, float* __restrict__ C)
{
    gemm_body<0>(A, W, bias, C, MTOK, DIM, DIM);
}

// ================ all-fp16 flash attention ==================================
// ABQ=64 rows/CTA, 4 warps x 16 rows; BK=64; double-buffered cp.async.
// Register-resident P; K via ldmatrix, V via ldmatrix.trans.
#define ABQ 64
#define ABK 64
#define KPH 136      // K pitch (halves) = 272B = 68w == 4 mod 32 (LDSM-safe)
#define VPH 136      // V pitch (halves)

#define SMB_K0 0
#define SMB_K1 (SMB_K0 + ABK * KPH * 2)      // 17408
#define SMB_V0 (SMB_K1 + ABK * KPH * 2)      // 34816
#define SMB_V1 (SMB_V0 + ABK * VPH * 2)      // 52224
#define SMB_MK (SMB_V1 + ABK * VPH * 2)      // 69632
#define ATT_BYTES (SMB_MK + 512)             // 70144

__global__ __launch_bounds__(128, 3) void attn_mma(
    const __half* __restrict__ Qm, const __half* __restrict__ Km,
    const __half* __restrict__ Vm, const int* __restrict__ mask,
    __half* __restrict__ ctx)
{
    extern __shared__ char smc[];
    const uint32_t sb = smem_u32(smc);
    const int tid = threadIdx.x, wid = tid >> 5, lane = tid & 31;
    const int g = lane >> 2, t = lane & 3;
    const int b = blockIdx.z, h = blockIdx.y, q0 = blockIdx.x * ABQ;
    const int wrow = wid * 16;
    const float scale = 0.08838834764831845f;   // 1/sqrt(128)
    const int NBLK = QLEN / ABK;                // 32

    const uint32_t koff =
        (((lane & 7) + 8 * (lane >> 4)) * KPH + 8 * ((lane >> 3) & 1)) * 2;
    const uint32_t voff =
        (((lane & 7) + 8 * ((lane >> 3) & 1)) * VPH + 8 * (lane >> 4)) * 2;

    auto load_kv = [&](int blk) {
        int bi = blk & 1;
        const __half* Kg = Km + ((size_t)(b * QLEN) + blk * ABK) * DIM + h * DHD;
        const __half* Vg = Vm + ((size_t)(b * QLEN) + blk * ABK) * DIM + h * DHD;
        uint32_t kbase = sb + (bi ? SMB_K1 : SMB_K0);
        uint32_t vbase = sb + (bi ? SMB_V1 : SMB_V0);
#pragma unroll
        for (int i = 0; i < 8; ++i) {          // K: 1024 chunks (64 rows x 16)
            int c = tid + i * 128;
            int r = c >> 4, c8 = c & 15;
            CP_ASYNC16(kbase + (r * KPH + c8 * 8) * 2, Kg + (size_t)r * DIM + c8 * 8);
        }
#pragma unroll
        for (int i = 0; i < 8; ++i) {          // V: 1024 chunks
            int c = tid + i * 128;
            int r = c >> 4, c8 = c & 15;
            CP_ASYNC16(vbase + (r * VPH + c8 * 8) * 2, Vg + (size_t)r * DIM + c8 * 8);
        }
        if (tid < 16)
            CP_ASYNC16(sb + SMB_MK + bi * 256 + tid * 16,
                       mask + b * QLEN + blk * ABK + tid * 4);
        CP_COMMIT();
    };

    uint32_t qa[8][4];
    {
        const __half* Qg = Qm + ((size_t)(b * QLEN) + q0 + wrow) * DIM + h * DHD;
#pragma unroll
        for (int kk = 0; kk < 8; ++kk) {
            int ko = kk * 16;
            qa[kk][0] = *(const uint32_t*)&Qg[(size_t)g * DIM + ko + 2 * t];
            qa[kk][1] = *(const uint32_t*)&Qg[(size_t)(g + 8) * DIM + ko + 2 * t];
            qa[kk][2] = *(const uint32_t*)&Qg[(size_t)g * DIM + ko + 8 + 2 * t];
            qa[kk][3] = *(const uint32_t*)&Qg[(size_t)(g + 8) * DIM + ko + 8 + 2 * t];
        }
    }

    float oacc[16][4];
#pragma unroll
    for (int nf = 0; nf < 16; ++nf)
#pragma unroll
        for (int q = 0; q < 4; ++q) oacc[nf][q] = 0.f;
    float mrow0 = -1e30f, mrow1 = -1e30f, lrow0 = 0.f, lrow1 = 0.f;

    load_kv(0); load_kv(1);

    for (int blk = 0; blk < NBLK; ++blk) {
        CP_WAIT(1);
        __syncthreads();
        const int bi = blk & 1;
        const uint32_t kbase = sb + (bi ? SMB_K1 : SMB_K0);
        const uint32_t vbase = sb + (bi ? SMB_V1 : SMB_V0);
        const int* mk = (const int*)(smc + SMB_MK + bi * 256);

        float sacc[8][4];
#pragma unroll
        for (int nf = 0; nf < 8; ++nf)
#pragma unroll
            for (int q = 0; q < 4; ++q) sacc[nf][q] = 0.f;

#pragma unroll
        for (int kk = 0; kk < 8; ++kk) {
            uint32_t bb[4][4];
#pragma unroll
            for (int p = 0; p < 4; ++p)
                LDSM_X4(bb[p][0], bb[p][1], bb[p][2], bb[p][3],
                        kbase + koff + p * (16 * KPH * 2) + kk * 32);
#pragma unroll
            for (int nf = 0; nf < 8; ++nf)
                mma_fp16(sacc[nf], qa[kk],
                         bb[nf >> 1][(nf & 1) * 2], bb[nf >> 1][(nf & 1) * 2 + 1]);
        }

        float pm0 = -1e30f, pm1 = -1e30f;
#pragma unroll
        for (int nf = 0; nf < 8; ++nf) {
            int j0 = nf * 8 + 2 * t, j1 = j0 + 1;
            bool a0 = mk[j0] != 0, a1 = mk[j1] != 0;
            sacc[nf][0] = a0 ? sacc[nf][0] * scale : -1e30f;
            sacc[nf][1] = a1 ? sacc[nf][1] * scale : -1e30f;
            sacc[nf][2] = a0 ? sacc[nf][2] * scale : -1e30f;
            sacc[nf][3] = a1 ? sacc[nf][3] * scale : -1e30f;
            pm0 = fmaxf(pm0, fmaxf(sacc[nf][0], sacc[nf][1]));
            pm1 = fmaxf(pm1, fmaxf(sacc[nf][2], sacc[nf][3]));
        }
        pm0 = fmaxf(pm0, __shfl_xor_sync(0xFFFFFFFFu, pm0, 1));
        pm0 = fmaxf(pm0, __shfl_xor_sync(0xFFFFFFFFu, pm0, 2));
        pm1 = fmaxf(pm1, __shfl_xor_sync(0xFFFFFFFFu, pm1, 1));
        pm1 = fmaxf(pm1, __shfl_xor_sync(0xFFFFFFFFu, pm1, 2));

        float mnew0 = fmaxf(mrow0, pm0), mnew1 = fmaxf(mrow1, pm1);
        float corr0 = __expf(mrow0 - mnew0), corr1 = __expf(mrow1 - mnew1);
#pragma unroll
        for (int nf = 0; nf < 16; ++nf) {
            oacc[nf][0] *= corr0; oacc[nf][1] *= corr0;
            oacc[nf][2] *= corr1; oacc[nf][3] *= corr1;
        }

        float ps0 = 0.f, ps1 = 0.f;
#pragma unroll
        for (int nf = 0; nf < 8; ++nf) {
            sacc[nf][0] = __expf(sacc[nf][0] - mnew0);
            sacc[nf][1] = __expf(sacc[nf][1] - mnew0);
            sacc[nf][2] = __expf(sacc[nf][2] - mnew1);
            sacc[nf][3] = __expf(sacc[nf][3] - mnew1);
            ps0 += sacc[nf][0] + sacc[nf][1];
            ps1 += sacc[nf][2] + sacc[nf][3];
        }
        ps0 += __shfl_xor_sync(0xFFFFFFFFu, ps0, 1);
        ps0 += __shfl_xor_sync(0xFFFFFFFFu, ps0, 2);
        ps1 += __shfl_xor_sync(0xFFFFFFFFu, ps1, 1);
        ps1 += __shfl_xor_sync(0xFFFFFFFFu, ps1, 2);
        lrow0 = lrow0 * corr0 + ps0;
        lrow1 = lrow1 * corr1 + ps1;
        mrow0 = mnew0; mrow1 = mnew1;

#pragma unroll
        for (int kk2 = 0; kk2 < 4; ++kk2) {
            uint32_t pa[4];
            __half2 hp;
            hp = __floats2half2_rn(sacc[2 * kk2][0],     sacc[2 * kk2][1]);     pa[0] = *(uint32_t*)&hp;
            hp = __floats2half2_rn(sacc[2 * kk2][2],     sacc[2 * kk2][3]);     pa[1] = *(uint32_t*)&hp;
            hp = __floats2half2_rn(sacc[2 * kk2 + 1][0], sacc[2 * kk2 + 1][1]); pa[2] = *(uint32_t*)&hp;
            hp = __floats2half2_rn(sacc[2 * kk2 + 1][2], sacc[2 * kk2 + 1][3]); pa[3] = *(uint32_t*)&hp;
#pragma unroll
            for (int p = 0; p < 8; ++p) {
                uint32_t v0, v1, v2, v3;
                LDSM_X4T(v0, v1, v2, v3,
                         vbase + voff + p * 32 + kk2 * (16 * VPH * 2));
                mma_fp16(oacc[2 * p],     pa, v0, v1);
                mma_fp16(oacc[2 * p + 1], pa, v2, v3);
            }
        }
        __syncthreads();
        if (blk + 2 < NBLK) load_kv(blk + 2);
        else CP_COMMIT();
    }

    float inv0 = 1.f / lrow0, inv1 = 1.f / lrow1;
    __half* Ob = ctx + ((size_t)(b * QLEN) + q0 + wrow) * DIM + h * DHD;
#pragma unroll
    for (int nf = 0; nf < 16; ++nf) {
        int col = nf * 8 + 2 * t;
        __half2 h0 = __floats2half2_rn(oacc[nf][0] * inv0, oacc[nf][1] * inv0);
        __half2 h1 = __floats2half2_rn(oacc[nf][2] * inv1, oacc[nf][3] * inv1);
        *(uint32_t*)&Ob[(size_t)g * DIM + col]       = *(uint32_t*)&h0;
        *(uint32_t*)&Ob[(size_t)(g + 8) * DIM + col] = *(uint32_t*)&h1;
    }
}

// ---------------- launch -----------------------------------------------------
extern "C" void kernel_launch(void* const* d_in, const int* in_sizes, int n_in,
                              void* d_out, int out_size)
{
    const float* x    = (const float*)d_in[0];
    const int*   mask = (const int*)d_in[1];
    const float* wq   = (const float*)d_in[2];
    const float* bq   = (const float*)d_in[3];
    const float* wk   = (const float*)d_in[4];
    const float* bk   = (const float*)d_in[5];
    const float* wv   = (const float*)d_in[6];
    const float* bv   = (const float*)d_in[7];
    const float* wo   = (const float*)d_in[8];
    const float* bo   = (const float*)d_in[9];
    float* out = (float*)d_out;

    __half *gxh, *gwh, *gqh, *gkh, *gvh, *gctxh;
    cudaGetSymbolAddress((void**)&gxh,   g_xh);
    cudaGetSymbolAddress((void**)&gwh,   g_wh);
    cudaGetSymbolAddress((void**)&gqh,   g_qh);
    cudaGetSymbolAddress((void**)&gkh,   g_kh);
    cudaGetSymbolAddress((void**)&gvh,   g_vh);
    cudaGetSymbolAddress((void**)&gctxh, g_ctxh);
    __half* gwq = gwh;
    __half* gwk = gwh + (size_t)DIM * DIM;
    __half* gwv = gwh + 2 * (size_t)DIM * DIM;
    __half* gwo = gwh + 3 * (size_t)DIM * DIM;

    cvt_flat<<<(NTOT4 + 255) / 256, 256>>>(
        (const float4*)x, (const float4*)wq, (const float4*)wk,
        (const float4*)wv, (const float4*)wo,
        (uint2*)gxh, (uint2*)gwq, (uint2*)gwk, (uint2*)gwv, (uint2*)gwo);

    cudaFuncSetAttribute(gemm_qkv, cudaFuncAttributeMaxDynamicSharedMemorySize, GSMEM_BYTES);
    cudaFuncSetAttribute(gemm_out, cudaFuncAttributeMaxDynamicSharedMemorySize, GSMEM_BYTES);
    cudaFuncSetAttribute(attn_mma, cudaFuncAttributeMaxDynamicSharedMemorySize, ATT_BYTES);

    dim3 qkv_grid(DIM / 128, MTOK / 128, 3);   // (16, 32, 3) = 1536 CTAs
    gemm_qkv<<<qkv_grid, 256, GSMEM_BYTES>>>(gxh, gwq, gwk, gwv, bq, bk, bv,
                                             gqh, gkh, gvh);

    attn_mma<<<dim3(QLEN / ABQ, NH, BSZ), 128, ATT_BYTES>>>(gqh, gkh, gvh, mask, gctxh);

    dim3 gemm_grid(DIM / 128, MTOK / 128);     // (16, 32) = 512 CTAs
    gemm_out<<<gemm_grid, 256, GSMEM_BYTES>>>(gctxh, gwo, bo, out);
}

// round 17
// speedup vs baseline: 1.0660x; 1.0038x over previous
#include <cuda_runtime.h>
#include <cuda_fp16.h>
#include <cstdint>

#define BSZ   2
#define QLEN  2048
#define DIM   2048
#define NH    16
#define DHD   128
#define MTOK  (BSZ * QLEN)   // 4096

// ---------------- scratch (static device memory; no allocation) -------------
__device__ __half g_xh[(size_t)MTOK * DIM];          // fp16 input
__device__ __half g_wh[4][(size_t)DIM * DIM];        // fp16 weights
__device__ __half g_qh[(size_t)MTOK * DIM];          // fp16 Q
__device__ __half g_kh[(size_t)MTOK * DIM];          // fp16 K
__device__ __half g_vh[(size_t)MTOK * DIM];          // fp16 V
__device__ __half g_ctxh[(size_t)MTOK * DIM];        // fp16 ctx

// ======================= helpers =============================================
#define CP_ASYNC16(dst, src) \
    asm volatile("cp.async.cg.shared.global [%0], [%1], 16;" :: "r"(dst), "l"(src))
#define CP_COMMIT() asm volatile("cp.async.commit_group;" ::: "memory")
#define CP_WAIT(n)  asm volatile("cp.async.wait_group %0;" :: "n"(n) : "memory")

__device__ __forceinline__ uint32_t smem_u32(const void* p) {
    uint32_t a;
    asm("{ .reg .u64 t; cvta.to.shared.u64 t, %1; cvt.u32.u64 %0, t; }"
        : "=r"(a) : "l"(p));
    return a;
}

__device__ __forceinline__ void mma_fp16(float* c, const uint32_t* a,
                                         uint32_t b0, uint32_t b1) {
    asm volatile(
        "mma.sync.aligned.m16n8k16.row.col.f32.f16.f16.f32 "
        "{%0,%1,%2,%3}, {%4,%5,%6,%7}, {%8,%9}, {%0,%1,%2,%3};"
        : "+f"(c[0]), "+f"(c[1]), "+f"(c[2]), "+f"(c[3])
        : "r"(a[0]), "r"(a[1]), "r"(a[2]), "r"(a[3]), "r"(b0), "r"(b1));
}

__device__ __forceinline__ float ex2(float x) {
    float r;
    asm("ex2.approx.f32 %0, %1;" : "=f"(r) : "f"(x));
    return r;
}

#define LDSM_X4(r0, r1, r2, r3, addr) \
    asm volatile("ldmatrix.sync.aligned.m8n8.x4.shared.b16 {%0,%1,%2,%3}, [%4];" \
        : "=r"(r0), "=r"(r1), "=r"(r2), "=r"(r3) : "r"(addr))
#define LDSM_X4T(r0, r1, r2, r3, addr) \
    asm volatile("ldmatrix.sync.aligned.m8n8.x4.trans.shared.b16 {%0,%1,%2,%3}, [%4];" \
        : "=r"(r0), "=r"(r1), "=r"(r2), "=r"(r3) : "r"(addr))

// ------------- flat fused fp32 -> fp16 conversion (all 5 tensors) -----------
#define NX4 (MTOK * DIM / 4)    // 2,097,152
#define NW4 (DIM * DIM / 4)     // 1,048,576
#define NTOT4 (NX4 + 4 * NW4)   // 6,291,456

__global__ __launch_bounds__(256) void cvt_flat(
    const float4* __restrict__ x,  const float4* __restrict__ w0,
    const float4* __restrict__ w1, const float4* __restrict__ w2,
    const float4* __restrict__ w3,
    uint2* __restrict__ ox,  uint2* __restrict__ o0, uint2* __restrict__ o1,
    uint2* __restrict__ o2,  uint2* __restrict__ o3)
{
    int i = blockIdx.x * 256 + threadIdx.x;
    if (i >= NTOT4) return;
    const float4* in;
    uint2* out;
    int off;
    if (i < NX4) { in = x; out = ox; off = i; }
    else {
        int j = i - NX4;
        int seg = j / NW4;                 // compile-time divisor
        off = j - seg * NW4;
        in  = (seg == 0) ? w0 : (seg == 1) ? w1 : (seg == 2) ? w2 : w3;
        out = (seg == 0) ? o0 : (seg == 1) ? o1 : (seg == 2) ? o2 : o3;
    }
    float4 v = in[off];
    __half2 h0 = __floats2half2_rn(v.x, v.y);
    __half2 h1 = __floats2half2_rn(v.z, v.w);
    out[off] = make_uint2(*(uint32_t*)&h0, *(uint32_t*)&h1);
}

// ================ fp16 mma GEMM: C = A @ W^T + bias =========================
// CTA 128(m) x 128(n), BK=64 halves. 8 warps (2m x 4n), warp tile 64x32.
// ldmatrix.x4 fragment loads. 3-stage cp.async ring, 110.6KB smem -> 2 CTA/SM.
#define HPITCH   72                          // halves/row (144B = 36w ==4 mod 32)
#define A_HALVES (128 * HPITCH)              // 9216
#define STAGE_BYTES (2 * A_HALVES * 2)       // 36864 (A then W)
#define NSTAGE   3
#define GSMEM_BYTES (NSTAGE * STAGE_BYTES)   // 110592

// MODE: 0 = float out, 1 = half out
template <int MODE>
__device__ __forceinline__ void gemm_body(
    const __half* __restrict__ A, const __half* __restrict__ W,
    const float* __restrict__ bias, void* __restrict__ Cv,
    int M, int N, int K)
{
    extern __shared__ char smc[];
    const uint32_t sb = smem_u32(smc);
    const int tid  = threadIdx.x;
    const int wid  = tid >> 5, lane = tid & 31;
    const int g    = lane >> 2, t = lane & 3;
    const int wm   = wid >> 2;          // 0..1
    const int wn   = wid & 3;           // 0..3
    const int m0   = blockIdx.y * 128;
    const int n0   = blockIdx.x * 128;
    const int NT   = K >> 6;            // 32

    const uint32_t aoff = ((wm * 64 + (lane & 15)) * HPITCH + 8 * (lane >> 4)) * 2;
    const uint32_t boff = A_HALVES * 2 +
        ((wn * 32 + (lane & 7) + 8 * (lane >> 4)) * HPITCH + 8 * ((lane >> 3) & 1)) * 2;

    const __half* Abase = A + (size_t)m0 * K;
    const __half* Wbase = W + (size_t)n0 * K;

    auto load_stage = [&](int s) {
        uint32_t soff = sb + (s % NSTAGE) * STAGE_BYTES;
        const __half* Ag = Abase + s * 64;
        const __half* Wg = Wbase + s * 64;
#pragma unroll
        for (int i = 0; i < 8; ++i) {
            int c = tid + i * 256;             // 0..2047
            if (i < 4) {                        // A: 1024 chunks (128 rows x 8)
                int row = c >> 3, kc = c & 7;
                CP_ASYNC16(soff + (row * HPITCH + kc * 8) * 2,
                           Ag + (size_t)row * K + kc * 8);
            } else {                            // W: 1024 chunks
                int c2 = c - 1024;
                int row = c2 >> 3, kc = c2 & 7;
                CP_ASYNC16(soff + A_HALVES * 2 + (row * HPITCH + kc * 8) * 2,
                           Wg + (size_t)row * K + kc * 8);
            }
        }
        CP_COMMIT();
    };

    float acc[4][4][4];
#pragma unroll
    for (int mt = 0; mt < 4; ++mt)
#pragma unroll
        for (int nf = 0; nf < 4; ++nf)
#pragma unroll
            for (int q = 0; q < 4; ++q) acc[mt][nf][q] = 0.f;

    load_stage(0); load_stage(1);

    for (int tt = 0; tt < NT; ++tt) {
        CP_WAIT(1);
        __syncthreads();
        if (tt + 2 < NT) load_stage(tt + 2);
        else CP_COMMIT();

        const uint32_t stg = sb + (tt % NSTAGE) * STAGE_BYTES;

#pragma unroll
        for (int k16 = 0; k16 < 4; ++k16) {
            const uint32_t kb = k16 * 32;      // 16 halves
            uint32_t a[4][4];
#pragma unroll
            for (int mt = 0; mt < 4; ++mt)
                LDSM_X4(a[mt][0], a[mt][1], a[mt][2], a[mt][3],
                        stg + aoff + mt * (16 * HPITCH * 2) + kb);
            uint32_t bb[2][4];
#pragma unroll
            for (int p = 0; p < 2; ++p)
                LDSM_X4(bb[p][0], bb[p][1], bb[p][2], bb[p][3],
                        stg + boff + p * (16 * HPITCH * 2) + kb);
#pragma unroll
            for (int nf = 0; nf < 4; ++nf) {
                uint32_t b0 = bb[nf >> 1][(nf & 1) * 2];
                uint32_t b1 = bb[nf >> 1][(nf & 1) * 2 + 1];
                mma_fp16(acc[0][nf], a[0], b0, b1);
                mma_fp16(acc[1][nf], a[1], b0, b1);
                mma_fp16(acc[2][nf], a[2], b0, b1);
                mma_fp16(acc[3][nf], a[3], b0, b1);
            }
        }
    }

#pragma unroll
    for (int nf = 0; nf < 4; ++nf) {
        int col = n0 + wn * 32 + nf * 8 + t * 2;
        float2 bj = *(const float2*)&bias[col];
#pragma unroll
        for (int mt = 0; mt < 4; ++mt) {
            int r0 = m0 + wm * 64 + mt * 16 + g;
            float o0 = acc[mt][nf][0] + bj.x, o1 = acc[mt][nf][1] + bj.y;
            float o2 = acc[mt][nf][2] + bj.x, o3 = acc[mt][nf][3] + bj.y;
            if (MODE == 1) {
                __half* Ch = (__half*)Cv;
                __half2 h0 = __floats2half2_rn(o0, o1);
                __half2 h1 = __floats2half2_rn(o2, o3);
                *(uint32_t*)&Ch[(size_t)r0 * N + col]       = *(uint32_t*)&h0;
                *(uint32_t*)&Ch[(size_t)(r0 + 8) * N + col] = *(uint32_t*)&h1;
            } else {
                float* Cf = (float*)Cv;
                *(float2*)&Cf[(size_t)r0 * N + col]       = make_float2(o0, o1);
                *(float2*)&Cf[(size_t)(r0 + 8) * N + col] = make_float2(o2, o3);
            }
        }
    }
}

__global__ __launch_bounds__(256, 2) void gemm_qkv(
    const __half* __restrict__ A,
    const __half* __restrict__ W0, const __half* __restrict__ W1, const __half* __restrict__ W2,
    const float* __restrict__ b0, const float* __restrict__ b1, const float* __restrict__ b2,
    __half* __restrict__ C0, __half* __restrict__ C1, __half* __restrict__ C2)
{
    const int z = blockIdx.z;
    const __half* W = (z == 0) ? W0 : (z == 1) ? W1 : W2;
    const float*  B = (z == 0) ? b0 : (z == 1) ? b1 : b2;
    __half*       C = (z == 0) ? C0 : (z == 1) ? C1 : C2;
    gemm_body<1>(A, W, B, C, MTOK, DIM, DIM);
}

__global__ __launch_bounds__(256, 2) void gemm_out(
    const __half* __restrict__ A, const __half* __restrict__ W,
    const float* __restrict__ bias, float* __restrict__ C)
{
    gemm_body<0>(A, W, bias, C, MTOK, DIM, DIM);
}

// ================ all-fp16 flash attention ==================================
// ABQ=64 rows/CTA, 4 warps x 16 rows; BK=64; double-buffered cp.async.
// Register-resident P; K via ldmatrix, V via ldmatrix.trans.
// Softmax in log2 domain: scale pre-multiplied by log2(e), ex2 instead of expf.
#define ABQ 64
#define ABK 64
#define KPH 136      // K pitch (halves) = 272B = 68w == 4 mod 32 (LDSM-safe)
#define VPH 136      // V pitch (halves)

#define SMB_K0 0
#define SMB_K1 (SMB_K0 + ABK * KPH * 2)      // 17408
#define SMB_V0 (SMB_K1 + ABK * KPH * 2)      // 34816
#define SMB_V1 (SMB_V0 + ABK * VPH * 2)      // 52224
#define SMB_MK (SMB_V1 + ABK * VPH * 2)      // 69632
#define ATT_BYTES (SMB_MK + 512)             // 70144

__global__ __launch_bounds__(128, 3) void attn_mma(
    const __half* __restrict__ Qm, const __half* __restrict__ Km,
    const __half* __restrict__ Vm, const int* __restrict__ mask,
    __half* __restrict__ ctx)
{
    extern __shared__ char smc[];
    const uint32_t sb = smem_u32(smc);
    const int tid = threadIdx.x, wid = tid >> 5, lane = tid & 31;
    const int g = lane >> 2, t = lane & 3;
    const int b = blockIdx.z, h = blockIdx.y, q0 = blockIdx.x * ABQ;
    const int wrow = wid * 16;
    // 1/sqrt(128) * log2(e): softmax computed in base-2 domain (exact same math)
    const float scale = 0.12751744452004744f;
    const int NBLK = QLEN / ABK;                // 32

    const uint32_t koff =
        (((lane & 7) + 8 * (lane >> 4)) * KPH + 8 * ((lane >> 3) & 1)) * 2;
    const uint32_t voff =
        (((lane & 7) + 8 * ((lane >> 3) & 1)) * VPH + 8 * (lane >> 4)) * 2;

    auto load_kv = [&](int blk) {
        int bi = blk & 1;
        const __half* Kg = Km + ((size_t)(b * QLEN) + blk * ABK) * DIM + h * DHD;
        const __half* Vg = Vm + ((size_t)(b * QLEN) + blk * ABK) * DIM + h * DHD;
        uint32_t kbase = sb + (bi ? SMB_K1 : SMB_K0);
        uint32_t vbase = sb + (bi ? SMB_V1 : SMB_V0);
#pragma unroll
        for (int i = 0; i < 8; ++i) {          // K: 1024 chunks (64 rows x 16)
            int c = tid + i * 128;
            int r = c >> 4, c8 = c & 15;
            CP_ASYNC16(kbase + (r * KPH + c8 * 8) * 2, Kg + (size_t)r * DIM + c8 * 8);
        }
#pragma unroll
        for (int i = 0; i < 8; ++i) {          // V: 1024 chunks
            int c = tid + i * 128;
            int r = c >> 4, c8 = c & 15;
            CP_ASYNC16(vbase + (r * VPH + c8 * 8) * 2, Vg + (size_t)r * DIM + c8 * 8);
        }
        if (tid < 16)
            CP_ASYNC16(sb + SMB_MK + bi * 256 + tid * 16,
                       mask + b * QLEN + blk * ABK + tid * 4);
        CP_COMMIT();
    };

    uint32_t qa[8][4];
    {
        const __half* Qg = Qm + ((size_t)(b * QLEN) + q0 + wrow) * DIM + h * DHD;
#pragma unroll
        for (int kk = 0; kk < 8; ++kk) {
            int ko = kk * 16;
            qa[kk][0] = *(const uint32_t*)&Qg[(size_t)g * DIM + ko + 2 * t];
            qa[kk][1] = *(const uint32_t*)&Qg[(size_t)(g + 8) * DIM + ko + 2 * t];
            qa[kk][2] = *(const uint32_t*)&Qg[(size_t)g * DIM + ko + 8 + 2 * t];
            qa[kk][3] = *(const uint32_t*)&Qg[(size_t)(g + 8) * DIM + ko + 8 + 2 * t];
        }
    }

    float oacc[16][4];
#pragma unroll
    for (int nf = 0; nf < 16; ++nf)
#pragma unroll
        for (int q = 0; q < 4; ++q) oacc[nf][q] = 0.f;
    float mrow0 = -1e30f, mrow1 = -1e30f, lrow0 = 0.f, lrow1 = 0.f;

    load_kv(0); load_kv(1);

    for (int blk = 0; blk < NBLK; ++blk) {
        CP_WAIT(1);
        __syncthreads();
        const int bi = blk & 1;
        const uint32_t kbase = sb + (bi ? SMB_K1 : SMB_K0);
        const uint32_t vbase = sb + (bi ? SMB_V1 : SMB_V0);
        const int* mk = (const int*)(smc + SMB_MK + bi * 256);

        float sacc[8][4];
#pragma unroll
        for (int nf = 0; nf < 8; ++nf)
#pragma unroll
            for (int q = 0; q < 4; ++q) sacc[nf][q] = 0.f;

#pragma unroll
        for (int kk = 0; kk < 8; ++kk) {
            uint32_t bb[4][4];
#pragma unroll
            for (int p = 0; p < 4; ++p)
                LDSM_X4(bb[p][0], bb[p][1], bb[p][2], bb[p][3],
                        kbase + koff + p * (16 * KPH * 2) + kk * 32);
#pragma unroll
            for (int nf = 0; nf < 8; ++nf)
                mma_fp16(sacc[nf], qa[kk],
                         bb[nf >> 1][(nf & 1) * 2], bb[nf >> 1][(nf & 1) * 2 + 1]);
        }

        float pm0 = -1e30f, pm1 = -1e30f;
#pragma unroll
        for (int nf = 0; nf < 8; ++nf) {
            int j0 = nf * 8 + 2 * t, j1 = j0 + 1;
            bool a0 = mk[j0] != 0, a1 = mk[j1] != 0;
            sacc[nf][0] = a0 ? sacc[nf][0] * scale : -1e30f;
            sacc[nf][1] = a1 ? sacc[nf][1] * scale : -1e30f;
            sacc[nf][2] = a0 ? sacc[nf][2] * scale : -1e30f;
            sacc[nf][3] = a1 ? sacc[nf][3] * scale : -1e30f;
            pm0 = fmaxf(pm0, fmaxf(sacc[nf][0], sacc[nf][1]));
            pm1 = fmaxf(pm1, fmaxf(sacc[nf][2], sacc[nf][3]));
        }
        pm0 = fmaxf(pm0, __shfl_xor_sync(0xFFFFFFFFu, pm0, 1));
        pm0 = fmaxf(pm0, __shfl_xor_sync(0xFFFFFFFFu, pm0, 2));
        pm1 = fmaxf(pm1, __shfl_xor_sync(0xFFFFFFFFu, pm1, 1));
        pm1 = fmaxf(pm1, __shfl_xor_sync(0xFFFFFFFFu, pm1, 2));

        float mnew0 = fmaxf(mrow0, pm0), mnew1 = fmaxf(mrow1, pm1);
        float corr0 = ex2(mrow0 - mnew0), corr1 = ex2(mrow1 - mnew1);
#pragma unroll
        for (int nf = 0; nf < 16; ++nf) {
            oacc[nf][0] *= corr0; oacc[nf][1] *= corr0;
            oacc[nf][2] *= corr1; oacc[nf][3] *= corr1;
        }

        float ps0 = 0.f, ps1 = 0.f;
#pragma unroll
        for (int nf = 0; nf < 8; ++nf) {
            sacc[nf][0] = ex2(sacc[nf][0] - mnew0);
            sacc[nf][1] = ex2(sacc[nf][1] - mnew0);
            sacc[nf][2] = ex2(sacc[nf][2] - mnew1);
            sacc[nf][3] = ex2(sacc[nf][3] - mnew1);
            ps0 += sacc[nf][0] + sacc[nf][1];
            ps1 += sacc[nf][2] + sacc[nf][3];
        }
        ps0 += __shfl_xor_sync(0xFFFFFFFFu, ps0, 1);
        ps0 += __shfl_xor_sync(0xFFFFFFFFu, ps0, 2);
        ps1 += __shfl_xor_sync(0xFFFFFFFFu, ps1, 1);
        ps1 += __shfl_xor_sync(0xFFFFFFFFu, ps1, 2);
        lrow0 = lrow0 * corr0 + ps0;
        lrow1 = lrow1 * corr1 + ps1;
        mrow0 = mnew0; mrow1 = mnew1;

#pragma unroll
        for (int kk2 = 0; kk2 < 4; ++kk2) {
            uint32_t pa[4];
            __half2 hp;
            hp = __floats2half2_rn(sacc[2 * kk2][0],     sacc[2 * kk2][1]);     pa[0] = *(uint32_t*)&hp;
            hp = __floats2half2_rn(sacc[2 * kk2][2],     sacc[2 * kk2][3]);     pa[1] = *(uint32_t*)&hp;
            hp = __floats2half2_rn(sacc[2 * kk2 + 1][0], sacc[2 * kk2 + 1][1]); pa[2] = *(uint32_t*)&hp;
            hp = __floats2half2_rn(sacc[2 * kk2 + 1][2], sacc[2 * kk2 + 1][3]); pa[3] = *(uint32_t*)&hp;
#pragma unroll
            for (int p = 0; p < 8; ++p) {
                uint32_t v0, v1, v2, v3;
                LDSM_X4T(v0, v1, v2, v3,
                         vbase + voff + p * 32 + kk2 * (16 * VPH * 2));
                mma_fp16(oacc[2 * p],     pa, v0, v1);
                mma_fp16(oacc[2 * p + 1], pa, v2, v3);
            }
        }
        __syncthreads();
        if (blk + 2 < NBLK) load_kv(blk + 2);
        else CP_COMMIT();
    }

    float inv0 = 1.f / lrow0, inv1 = 1.f / lrow1;
    __half* Ob = ctx + ((size_t)(b * QLEN) + q0 + wrow) * DIM + h * DHD;
#pragma unroll
    for (int nf = 0; nf < 16; ++nf) {
        int col = nf * 8 + 2 * t;
        __half2 h0 = __floats2half2_rn(oacc[nf][0] * inv0, oacc[nf][1] * inv0);
        __half2 h1 = __floats2half2_rn(oacc[nf][2] * inv1, oacc[nf][3] * inv1);
        *(uint32_t*)&Ob[(size_t)g * DIM + col]       = *(uint32_t*)&h0;
        *(uint32_t*)&Ob[(size_t)(g + 8) * DIM + col] = *(uint32_t*)&h1;
    }
}

// ---------------- launch -----------------------------------------------------
extern "C" void kernel_launch(void* const* d_in, const int* in_sizes, int n_in,
                              void* d_out, int out_size)
{
    const float* x    = (const float*)d_in[0];
    const int*   mask = (const int*)d_in[1];
    const float* wq   = (const float*)d_in[2];
    const float* bq   = (const float*)d_in[3];
    const float* wk   = (const float*)d_in[4];
    const float* bk   = (const float*)d_in[5];
    const float* wv   = (const float*)d_in[6];
    const float* bv   = (const float*)d_in[7];
    const float* wo   = (const float*)d_in[8];
    const float* bo   = (const float*)d_in[9];
    float* out = (float*)d_out;

    __half *gxh, *gwh, *gqh, *gkh, *gvh, *gctxh;
    cudaGetSymbolAddress((void**)&gxh,   g_xh);
    cudaGetSymbolAddress((void**)&gwh,   g_wh);
    cudaGetSymbolAddress((void**)&gqh,   g_qh);
    cudaGetSymbolAddress((void**)&gkh,   g_kh);
    cudaGetSymbolAddress((void**)&gvh,   g_vh);
    cudaGetSymbolAddress((void**)&gctxh, g_ctxh);
    __half* gwq = gwh;
    __half* gwk = gwh + (size_t)DIM * DIM;
    __half* gwv = gwh + 2 * (size_t)DIM * DIM;
    __half* gwo = gwh + 3 * (size_t)DIM * DIM;

    cvt_flat<<<(NTOT4 + 255) / 256, 256>>>(
        (const float4*)x, (const float4*)wq, (const float4*)wk,
        (const float4*)wv, (const float4*)wo,
        (uint2*)gxh, (uint2*)gwq, (uint2*)gwk, (uint2*)gwv, (uint2*)gwo);

    cudaFuncSetAttribute(gemm_qkv, cudaFuncAttributeMaxDynamicSharedMemorySize, GSMEM_BYTES);
    cudaFuncSetAttribute(gemm_out, cudaFuncAttributeMaxDynamicSharedMemorySize, GSMEM_BYTES);
    cudaFuncSetAttribute(attn_mma, cudaFuncAttributeMaxDynamicSharedMemorySize, ATT_BYTES);

    dim3 qkv_grid(DIM / 128, MTOK / 128, 3);   // (16, 32, 3) = 1536 CTAs
    gemm_qkv<<<qkv_grid, 256, GSMEM_BYTES>>>(gxh, gwq, gwk, gwv, bq, bk, bv,
                                             gqh, gkh, gvh);

    attn_mma<<<dim3(QLEN / ABQ, NH, BSZ), 128, ATT_BYTES>>>(gqh, gkh, gvh, mask, gctxh);

    dim3 gemm_grid(DIM / 128, MTOK / 128);     // (16, 32) = 512 CTAs
    gemm_out<<<gemm_grid, 256, GSMEM_BYTES>>>(gctxh, gwo, bo, out);
}